// round 12
// baseline (speedup 1.0000x reference)
#include <cuda_runtime.h>

// Fixed problem shapes
#define Tt 2000
#define Bb 64
#define Vv 163
#define Lmax 200
#define NEGV (-1e30f)
#define LOG2E 1.4426950408889634f
#define LN2 0.6931471805599453f

// Wavefront config
#define CC 8                 // steps per chunk (consumer release granularity)
#define NCW 7                // consumer warps
#define OWNL 29              // owned pairs per consumer warp (lanes 0..28)
#define RD 64                // row ring depth (rows)
#define BD 128               // boundary ring depth (steps)
#define RSTR 164             // padded row stride (floats)
#define THR 256              // 7 consumers + 1 producer

__device__ float g_lse2[Bb * Tt];   // transposed [b][t]
__device__ float g_llraw[Bb];
__device__ float g_losses[Bb];

__device__ __forceinline__ float ex2f_(float x) {
    float y; asm("ex2.approx.f32 %0, %1;" : "=f"(y) : "f"(x)); return y;
}
__device__ __forceinline__ float lg2f_(float x) {
    float y; asm("lg2.approx.f32 %0, %1;" : "=f"(y) : "f"(x)); return y;
}
__device__ __forceinline__ float lae2_(float a, float b) {
    float M = fmaxf(a, b), m = fminf(a, b);
    return M + lg2f_(1.0f + ex2f_(m - M));
}
__device__ __forceinline__ unsigned saddr_(const void* p) {
    return (unsigned)__cvta_generic_to_shared(p);
}
__device__ __forceinline__ int ld_acq_(const int* p) {
    int v;
    asm volatile("ld.acquire.cta.shared.b32 %0, [%1];"
                 : "=r"(v) : "r"(saddr_(p)) : "memory");
    return v;
}
__device__ __forceinline__ void st_rel_(int* p, int v) {
    asm volatile("st.release.cta.shared.b32 [%0], %1;"
                 :: "r"(saddr_(p)), "r"(v) : "memory");
}

// ---------------------------------------------------------------------------
// Kernel 1: per-(t,b) log2-sum-exp2 over vocab. One warp per row (parallel).
// ---------------------------------------------------------------------------
__global__ void lse_kernel(const float* __restrict__ logits) {
    int w = (blockIdx.x * blockDim.x + threadIdx.x) >> 5;
    int lane = threadIdx.x & 31;
    if (w >= Tt * Bb) return;
    const float* row = logits + (size_t)w * Vv;
    float y[6];
    float m = NEGV;
#pragma unroll
    for (int i = 0; i < 6; i++) {
        int v = lane + 32 * i;
        y[i] = (v < Vv) ? row[v] * LOG2E : NEGV;
        m = fmaxf(m, y[i]);
    }
#pragma unroll
    for (int o = 16; o > 0; o >>= 1) m = fmaxf(m, __shfl_xor_sync(0xffffffffu, m, o));
    float sv = 0.f;
#pragma unroll
    for (int i = 0; i < 6; i++) sv += ex2f_(y[i] - m);
#pragma unroll
    for (int o = 16; o > 0; o >>= 1) sv += __shfl_xor_sync(0xffffffffu, sv, o);
    if (lane == 0) {
        int t = w / Bb, b = w % Bb;
        g_lse2[b * Tt + t] = m + lg2f_(sv);
    }
}

// ---------------------------------------------------------------------------
// Kernel 2: CTC forward wavefront on RAW log2-logits. One CTA per utterance.
// Warp 7 = producer: ONLY stages logit rows gmem->smem ring (no reduction).
// Warps 0..6 = consumers: decoupled left->right wavefront, no block barriers.
// Normalization corrected in finalize via g_lse2.
// ---------------------------------------------------------------------------
__global__ void __launch_bounds__(THR, 1) ctc_alpha_kernel(
    const float* __restrict__ logits,
    const int*   __restrict__ labels,
    const int*   __restrict__ act_lens,
    const int*   __restrict__ label_lens)
{
    const int b    = blockIdx.x;
    const int tid  = threadIdx.x;
    const int lane = tid & 31;
    const int w    = tid >> 5;

    __shared__ float  rows[RD * RSTR];       // raw logit rows, ring by t
    __shared__ float  bring[NCW][BD];        // boundary aO rings, by step t
    __shared__ float2 fin[NCW * OWNL];       // final (aE,aO) per pair
    __shared__ int    cons_t[NCW];           // last completed step per warp
    __shared__ int    prod_rows;             // highest staged row index

    const int act_len   = act_lens[b];
    const int label_len = label_lens[b];
    const float* base = logits + (size_t)b * Vv;
    const size_t gstr = (size_t)Bb * Vv;

    if (tid < NCW) cons_t[tid] = 0;
    if (tid == 0)  prod_rows = 0;

    // consumer setup + t=0 init
    int  lab = 1;  bool allow = false;  float aE = NEGV, aO = NEGV;
    if (w < NCW) {
        const int p  = OWNL * w + lane;              // pair index (lanes 29-31 junk)
        const int pc = min(p, Lmax - 1);
        lab = labels[b * Lmax + pc];
        allow = (p > 0) && (lab != labels[b * Lmax + max(pc - 1, 0)]);
        if (p == 0) {                                 // states 0,1 at t=0
            aE = base[0]   * LOG2E;
            aO = base[lab] * LOG2E;                   // label_len >= 100 always
        }
        if (lane == OWNL - 1) bring[w][0] = aO;       // boundary at t=0
    }
    __syncthreads();   // orders init stores; last block-wide sync until the end

    if (w == NCW) {
        // ------------- producer warp: stage rows only -------------
        int t = 1;                                    // row 0 never staged
        while (t < act_len) {
            int bend = min(t + 4, act_len);
            if (bend - 1 > RD - 4) {                  // ring-space gate
                int lim = bend - 1 - RD + 4;
                while (ld_acq_(&cons_t[NCW - 1]) < lim) __nanosleep(32);
            }
#pragma unroll 1
            for (int r = t; r < bend; ++r) {
                const float* rp = base + (size_t)r * gstr;
                float* d = &rows[(r & (RD - 1)) * RSTR];
                float v0 = rp[lane],      v1 = rp[32 + lane];
                float v2 = rp[64 + lane], v3 = rp[96 + lane];
                float v4 = rp[128 + lane];
                float v5 = (lane < 3) ? rp[160 + lane] : 0.f;
                d[lane] = v0; d[32 + lane] = v1; d[64 + lane] = v2;
                d[96 + lane] = v3; d[128 + lane] = v4;
                if (lane < 3) d[160 + lane] = v5;
            }
            __syncwarp();                             // order all lanes' STS
            if (lane == 0) st_rel_(&prod_rows, bend - 1);
            t = bend;
        }
    } else {
        // ---------------- consumer warp w ----------------
        int t0 = 1;
        for (; t0 + CC - 1 <= act_len - 1; t0 += CC) {
            {   // gates
                int needR = t0 + CC - 1;
                if (ld_acq_(&prod_rows) < needR)
                    while (ld_acq_(&prod_rows) < needR) __nanosleep(32);
                if (w > 0) {
                    int needL = t0 + CC - 2;
                    if (ld_acq_(&cons_t[w - 1]) < needL)
                        while (ld_acq_(&cons_t[w - 1]) < needL) __nanosleep(32);
                }
            }
            // prefetch this chunk's lp's and boundaries (off the chain)
            float lpB[CC], lpL[CC], bnd[CC];
#pragma unroll
            for (int u = 0; u < CC; u++) {
                const float* rp = &rows[((t0 + u) & (RD - 1)) * RSTR];
                lpB[u] = rp[0]   * LOG2E;
                lpL[u] = rp[lab] * LOG2E;
                bnd[u] = (w > 0) ? bring[w - 1][(t0 + u - 1) & (BD - 1)] : NEGV;
            }
#pragma unroll
            for (int u = 0; u < CC; u++) {
                float aOp = __shfl_up_sync(0xffffffffu, aO, 1);
                float M1 = fmaxf(aO, aE), m1 = fminf(aO, aE);
                if (lane == 0) aOp = bnd[u];
                float c  = allow ? aOp : NEGV;
                float ME = fmaxf(aE, aOp), mE = fminf(aE, aOp);
                float nE = lg2f_(1.0f + ex2f_(mE - ME)) + (ME + lpB[u]);
                float M2 = fmaxf(M1, c), m2 = fminf(M1, c);
                float nO = lg2f_(1.0f + ex2f_(m1 - M2) + ex2f_(m2 - M2)) + (M2 + lpL[u]);
                aE = nE; aO = nO;
                if (lane == OWNL - 1) bring[w][(t0 + u) & (BD - 1)] = aO;
            }
            if (lane == OWNL - 1) st_rel_(&cons_t[w], t0 + CC - 1);
        }
        // tail
        if (t0 <= act_len - 1) {
            while (ld_acq_(&prod_rows) < act_len - 1) __nanosleep(32);
            if (w > 0)
                while (ld_acq_(&cons_t[w - 1]) < act_len - 2) __nanosleep(32);
            for (int t = t0; t <= act_len - 1; ++t) {
                const float* rp = &rows[(t & (RD - 1)) * RSTR];
                float lpB = rp[0] * LOG2E, lpL = rp[lab] * LOG2E;
                float bd  = (w > 0) ? bring[w - 1][(t - 1) & (BD - 1)] : NEGV;
                float aOp = __shfl_up_sync(0xffffffffu, aO, 1);
                float M1 = fmaxf(aO, aE), m1 = fminf(aO, aE);
                if (lane == 0) aOp = bd;
                float c  = allow ? aOp : NEGV;
                float ME = fmaxf(aE, aOp), mE = fminf(aE, aOp);
                float nE = lg2f_(1.0f + ex2f_(mE - ME)) + (ME + lpB);
                float M2 = fmaxf(M1, c), m2 = fminf(M1, c);
                float nO = lg2f_(1.0f + ex2f_(m1 - M2) + ex2f_(m2 - M2)) + (M2 + lpL);
                aE = nE; aO = nO;
                if (lane == OWNL - 1) bring[w][t & (BD - 1)] = aO;
            }
        }
        if (lane == OWNL - 1) st_rel_(&cons_t[w], act_len);  // done sentinel
        if (lane < OWNL) fin[OWNL * w + lane] = make_float2(aE, aO);
    }

    __syncthreads();
    if (tid == 0) {
        float al = fin[label_len].x;            // state 2L
        float ap = fin[label_len - 1].y;        // state 2L-1 (label_len >= 100)
        g_llraw[b] = lae2_(al, ap);             // raw log2 forward prob
    }
}

// ---------------------------------------------------------------------------
// Kernel 3: per-b normalization correction (fp64 sum of lse2) + loss
// ---------------------------------------------------------------------------
__global__ void finalize_kernel(const int* __restrict__ act_lens) {
    const int b = blockIdx.x, tid = threadIdx.x;
    const int n = act_lens[b];
    const float* pr = g_lse2 + (size_t)b * Tt;
    double sd = 0.0;
    for (int t = tid; t < n; t += 256) sd += (double)pr[t];
    __shared__ double red[256];
    red[tid] = sd; __syncthreads();
    for (int o = 128; o > 0; o >>= 1) {
        if (tid < o) red[tid] += red[tid + o];
        __syncthreads();
    }
    if (tid == 0)
        g_losses[b] = (float)((red[0] - (double)g_llraw[b]) * (double)LN2);
}

// ---------------------------------------------------------------------------
// Kernel 4: total = sum(losses) / sum(act_lens)
// ---------------------------------------------------------------------------
__global__ void reduce_kernel(const int* __restrict__ act_lens,
                              float* __restrict__ out)
{
    int lane = threadIdx.x;
    float l = g_losses[lane] + g_losses[lane + 32];
    float n = (float)act_lens[lane] + (float)act_lens[lane + 32];
#pragma unroll
    for (int o = 16; o > 0; o >>= 1) {
        l += __shfl_xor_sync(0xffffffffu, l, o);
        n += __shfl_xor_sync(0xffffffffu, n, o);
    }
    if (lane == 0) out[0] = l / n;
}

extern "C" void kernel_launch(void* const* d_in, const int* in_sizes, int n_in,
                              void* d_out, int out_size)
{
    const float* logits     = (const float*)d_in[0];
    const int*   labels     = (const int*)  d_in[1];
    const int*   act_lens   = (const int*)  d_in[2];
    const int*   label_lens = (const int*)  d_in[3];

    const int rows = Tt * Bb;
    lse_kernel<<<(rows * 32 + 255) / 256, 256>>>(logits);
    ctc_alpha_kernel<<<Bb, THR>>>(logits, labels, act_lens, label_lens);
    finalize_kernel<<<Bb, 256>>>(act_lens);
    reduce_kernel<<<1, 32>>>(act_lens, (float*)d_out);
}

// round 13
// speedup vs baseline: 3.0071x; 3.0071x over previous
#include <cuda_runtime.h>

#define Tt 2000
#define Bb 64
#define Vv 163
#define Lmax 200
#define NEGV (-1e30f)
#define LOG2E 1.4426950408889634f
#define LN2 0.6931471805599453f

#define UU 9
#define NWARP 9
#define HALO 9
#define OWNW 23
#define NSNAP 208
#define RSTR 164
#define THR (NWARP * 32)
#define NSTG 6

__device__ float  g_lse2[Bb * Tt];
__device__ float2 g_ab[2][Bb][NSNAP];
__device__ float  g_losses[Bb];

__device__ __forceinline__ float ex2f_(float x) {
    float y; asm("ex2.approx.f32 %0, %1;" : "=f"(y) : "f"(x)); return y;
}
__device__ __forceinline__ float lg2f_(float x) {
    float y; asm("lg2.approx.f32 %0, %1;" : "=f"(y) : "f"(x)); return y;
}
__device__ __forceinline__ float lae2_(float a, float b) {
    float M = fmaxf(a, b), m = fminf(a, b);
    return M + lg2f_(1.0f + ex2f_(m - M));
}
__device__ __forceinline__ float lae3_(float a, float b, float c) {
    float M1 = fmaxf(a, b), m1 = fminf(a, b);
    float M2 = fmaxf(M1, c), m2 = fminf(M1, c);
    return M2 + lg2f_(1.0f + ex2f_(m1 - M2) + ex2f_(m2 - M2));
}

__global__ void lse_kernel(const float* __restrict__ logits) {
    int w = (blockIdx.x * blockDim.x + threadIdx.x) >> 5;
    int lane = threadIdx.x & 31;
    if (w >= Tt * Bb) return;
    const float* row = logits + (size_t)w * Vv;
    float y[6];
    float m = NEGV;
#pragma unroll
    for (int i = 0; i < 6; i++) {
        int v = lane + 32 * i;
        y[i] = (v < Vv) ? row[v] * LOG2E : NEGV;
        m = fmaxf(m, y[i]);
    }
#pragma unroll
    for (int o = 16; o > 0; o >>= 1) m = fmaxf(m, __shfl_xor_sync(0xffffffffu, m, o));
    float sv = 0.f;
#pragma unroll
    for (int i = 0; i < 6; i++) sv += ex2f_(y[i] - m);
#pragma unroll
    for (int o = 16; o > 0; o >>= 1) sv += __shfl_xor_sync(0xffffffffu, sv, o);
    if (lane == 0) {
        int t = w / Bb, b = w % Bb;
        g_lse2[b * Tt + t] = m + lg2f_(sv);
    }
}

__global__ void __launch_bounds__(THR, 1) ctc_ab_kernel(
    const float* __restrict__ logits,
    const int*   __restrict__ labels,
    const int*   __restrict__ act_lens,
    const int*   __restrict__ label_lens)
{
    const int b    = blockIdx.x;
    const int dir  = blockIdx.y;
    const int tid  = threadIdx.x;
    const int lane = tid & 31;
    const int w    = tid >> 5;

    __shared__ float2 snap[2][NSNAP];
    __shared__ float  rbuf[3][UU * RSTR];

    const int act_len   = act_lens[b];
    const int label_len = label_lens[b];
    const int tm  = act_len >> 1;
    const int NST = dir ? (act_len - 1 - tm) : tm;

    const int  p = dir ? (OWNW * w + lane) : (OWNW * w - HALO + lane);
    const bool owner = dir ? (lane < OWNW && p < NSNAP)
                           : (lane >= HALO && p < NSNAP);

    const int  pc   = min(max(p, 0), Lmax - 1);
    const int  lab  = labels[b * Lmax + pc];
    const int  labn = labels[b * Lmax + min(pc + 1, Lmax - 1)];
    const bool allow  = (p > 0) && (lab != labels[b * Lmax + max(pc - 1, 0)]);
    const bool allown = (labn != lab);
    const bool vE = (p >= 0) && (p <= label_len);
    const bool vO = (p >= 0) && (p <  label_len);

    const float* base = logits + (size_t)b * Vv;
    const size_t gstr = (size_t)Bb * Vv;

    int su[NSTG], svv[NSTG]; bool sa[NSTG];
#pragma unroll
    for (int i = 0; i < NSTG; i++) {
        int idx = tid + i * THR;
        sa[i]  = idx < UU * Vv;
        su[i]  = idx / Vv;
        svv[i] = idx - su[i] * Vv;
    }

    for (int i = tid; i < NSNAP; i += THR) {
        snap[0][i] = make_float2(NEGV, NEGV);
        snap[1][i] = make_float2(NEGV, NEGV);
    }
    __syncthreads();
    if (tid == 0) {
        if (dir == 0) {
            int lab0 = labels[b * Lmax];
            snap[0][0] = make_float2(base[0] * LOG2E, base[lab0] * LOG2E);
        } else {
            snap[0][label_len]     = make_float2(0.f, NEGV);
            snap[0][label_len - 1] = make_float2(NEGV, 0.f);
        }
    }
    float g[NSTG];
#pragma unroll
    for (int i = 0; i < NSTG; i++) {
        if (sa[i]) {
            int j1 = min(su[i], NST - 1);
            int r1 = dir ? (act_len - 1 - j1) : (1 + j1);
            rbuf[0][su[i] * RSTR + svv[i]] = base[(size_t)r1 * gstr + svv[i]] * LOG2E;
            int j2 = min(UU + su[i], NST - 1);
            int r2 = dir ? (act_len - 1 - j2) : (1 + j2);
            g[i] = base[(size_t)r2 * gstr + svv[i]];
        }
    }
    __syncthreads();

    float aE = NEGV, aO = NEGV;
    int scur = 0, rcur = 0;
    for (int j0 = 0; j0 < NST; j0 += UU) {
        const int rnxt = (rcur + 1) % 3;
        const float* rb = rbuf[rcur];
        float lpB[UU], lpL[UU], lpLn[UU];
#pragma unroll
        for (int u = 0; u < UU; u++) {
            lpB[u] = rb[u * RSTR];
            lpL[u] = rb[u * RSTR + lab];
            if (dir) lpLn[u] = rb[u * RSTR + labn];
        }
#pragma unroll
        for (int i = 0; i < NSTG; i++)
            if (sa[i]) rbuf[rnxt][su[i] * RSTR + svv[i]] = g[i] * LOG2E;
#pragma unroll
        for (int i = 0; i < NSTG; i++) {
            if (sa[i]) {
                int j2 = min(j0 + 2 * UU + su[i], NST - 1);
                int r2 = dir ? (act_len - 1 - j2) : (1 + j2);
                g[i] = base[(size_t)r2 * gstr + svv[i]];
            }
        }

        float2 P = (p >= 0 && p < NSNAP) ? snap[scur][p] : make_float2(NEGV, NEGV);
        aE = P.x; aO = P.y;

        if (dir == 0) {
#pragma unroll
            for (int u = 0; u < UU; u++) {
                const bool live = (j0 + u) < NST;
                float aOp = __shfl_up_sync(0xffffffffu, aO, 1);
                float M1 = fmaxf(aO, aE), m1 = fminf(aO, aE);
                if (lane == 0) aOp = NEGV;
                float c  = allow ? aOp : NEGV;
                float ME = fmaxf(aE, aOp), mE = fminf(aE, aOp);
                float nE = lg2f_(1.0f + ex2f_(mE - ME)) + (ME + lpB[u]);
                float M2 = fmaxf(M1, c), m2 = fminf(M1, c);
                float nO = lg2f_(1.0f + ex2f_(m1 - M2) + ex2f_(m2 - M2)) + (M2 + lpL[u]);
                if (live) { aE = vE ? nE : NEGV; aO = vO ? nO : NEGV; }
            }
        } else {
#pragma unroll
            for (int u = 0; u < UU; u++) {
                const bool live = (j0 + u) < NST;
                float aEn = __shfl_down_sync(0xffffffffu, aE, 1);
                float aOn = __shfl_down_sync(0xffffffffu, aO, 1);
                float tE = aE + lpB[u];
                float tO = aO + lpL[u];
                if (lane == 31) { aEn = NEGV; aOn = NEGV; }
                float t2 = aEn + lpB[u];
                float t3 = allown ? (aOn + lpLn[u]) : NEGV;
                float nE = lae2_(tE, tO);
                float nO = lae3_(tO, t2, t3);
                if (live) { aE = vE ? nE : NEGV; aO = vO ? nO : NEGV; }
            }
        }

        if (owner) snap[scur ^ 1][p] = make_float2(aE, aO);
        __syncthreads();
        scur ^= 1;
        rcur = rnxt;
    }

    if (owner) g_ab[dir][b][p] = make_float2(aE, aO);
}

__global__ void finalize_kernel(const int* __restrict__ act_lens) {
    const int b = blockIdx.x, tid = threadIdx.x;
    const int n = act_lens[b];

    float x = NEGV, y = NEGV;
    if (tid < NSNAP) {
        float2 va = g_ab[0][b][tid];
        float2 vb = g_ab[1][b][tid];
        x = va.x + vb.x;
        y = va.y + vb.y;
    }
    __shared__ float redf[256];
    float m = fmaxf(x, y);
    redf[tid] = m; __syncthreads();
    for (int o = 128; o > 0; o >>= 1) {
        if (tid < o) redf[tid] = fmaxf(redf[tid], redf[tid + o]);
        __syncthreads();
    }
    const float gm = redf[0];
    __syncthreads();
    float sv = ex2f_(x - gm) + ex2f_(y - gm);
    redf[tid] = sv; __syncthreads();
    for (int o = 128; o > 0; o >>= 1) {
        if (tid < o) redf[tid] += redf[tid + o];
        __syncthreads();
    }
    const float ll2raw = gm + lg2f_(redf[0]);
    __syncthreads();

    const float* pr = g_lse2 + (size_t)b * Tt;
    double sd = 0.0;
    for (int t = tid; t < n; t += 256) sd += (double)pr[t];
    __shared__ double redd[256];
    redd[tid] = sd; __syncthreads();
    for (int o = 128; o > 0; o >>= 1) {
        if (tid < o) redd[tid] += redd[tid + o];
        __syncthreads();
    }
    if (tid == 0)
        g_losses[b] = (float)((redd[0] - (double)ll2raw) * (double)LN2);
}

__global__ void reduce_kernel(const int* __restrict__ act_lens,
                              float* __restrict__ out)
{
    int lane = threadIdx.x;
    float l = g_losses[lane] + g_losses[lane + 32];
    float n = (float)act_lens[lane] + (float)act_lens[lane + 32];
#pragma unroll
    for (int o = 16; o > 0; o >>= 1) {
        l += __shfl_xor_sync(0xffffffffu, l, o);
        n += __shfl_xor_sync(0xffffffffu, n, o);
    }
    if (lane == 0) out[0] = l / n;
}

extern "C" void kernel_launch(void* const* d_in, const int* in_sizes, int n_in,
                              void* d_out, int out_size)
{
    const float* logits     = (const float*)d_in[0];
    const int*   labels     = (const int*)  d_in[1];
    const int*   act_lens   = (const int*)  d_in[2];
    const int*   label_lens = (const int*)  d_in[3];

    const int rows = Tt * Bb;
    lse_kernel<<<(rows * 32 + 255) / 256, 256>>>(logits);
    ctc_ab_kernel<<<dim3(Bb, 2), THR>>>(logits, labels, act_lens, label_lens);
    finalize_kernel<<<Bb, 256>>>(act_lens);
    reduce_kernel<<<1, 32>>>(act_lens, (float*)d_out);
}

// round 14
// speedup vs baseline: 3.0077x; 1.0002x over previous
#include <cuda_runtime.h>

#define Tt 2000
#define Bb 64
#define Vv 163
#define Lmax 200
#define NEGV (-1e30f)
#define LOG2E 1.4426950408889634f
#define LN2 0.6931471805599453f

#define UU 9
#define NWARP 9
#define HALO 9
#define OWNW 23
#define NSNAP 208
#define RSTR 164
#define THR (NWARP * 32)
#define NSTG 6

__device__ float  g_lse2[Bb * Tt];
__device__ float2 g_ab[2][Bb][NSNAP];
__device__ float  g_losses[Bb];

__device__ __forceinline__ float ex2f_(float x) {
    float y; asm("ex2.approx.f32 %0, %1;" : "=f"(y) : "f"(x)); return y;
}
__device__ __forceinline__ float lg2f_(float x) {
    float y; asm("lg2.approx.f32 %0, %1;" : "=f"(y) : "f"(x)); return y;
}
__device__ __forceinline__ float lae2_(float a, float b) {
    float M = fmaxf(a, b), m = fminf(a, b);
    return M + lg2f_(1.0f + ex2f_(m - M));
}
__device__ __forceinline__ float lae3_(float a, float b, float c) {
    float M1 = fmaxf(a, b), m1 = fminf(a, b);
    float M2 = fmaxf(M1, c), m2 = fminf(M1, c);
    return M2 + lg2f_(1.0f + ex2f_(m1 - M2) + ex2f_(m2 - M2));
}

__global__ void lse_kernel(const float* __restrict__ logits) {
    int w = (blockIdx.x * blockDim.x + threadIdx.x) >> 5;
    int lane = threadIdx.x & 31;
    if (w >= Tt * Bb) return;
    const float* row = logits + (size_t)w * Vv;
    float y[6];
    float m = NEGV;
#pragma unroll
    for (int i = 0; i < 6; i++) {
        int v = lane + 32 * i;
        y[i] = (v < Vv) ? row[v] * LOG2E : NEGV;
        m = fmaxf(m, y[i]);
    }
#pragma unroll
    for (int o = 16; o > 0; o >>= 1) m = fmaxf(m, __shfl_xor_sync(0xffffffffu, m, o));
    float sv = 0.f;
#pragma unroll
    for (int i = 0; i < 6; i++) sv += ex2f_(y[i] - m);
#pragma unroll
    for (int o = 16; o > 0; o >>= 1) sv += __shfl_xor_sync(0xffffffffu, sv, o);
    if (lane == 0) {
        int t = w / Bb, b = w % Bb;
        g_lse2[b * Tt + t] = m + lg2f_(sv);
    }
}

__global__ void __launch_bounds__(THR, 1) ctc_ab_kernel(
    const float* __restrict__ logits,
    const int*   __restrict__ labels,
    const int*   __restrict__ act_lens,
    const int*   __restrict__ label_lens)
{
    const int b    = blockIdx.x;
    const int dir  = blockIdx.y;
    const int tid  = threadIdx.x;
    const int lane = tid & 31;
    const int w    = tid >> 5;

    __shared__ float2 snap[2][NSNAP];
    __shared__ float  rbuf[3][UU * RSTR];

    const int act_len   = act_lens[b];
    const int label_len = label_lens[b];
    const int tm  = act_len >> 1;
    const int NST = dir ? (act_len - 1 - tm) : tm;

    const int  p = dir ? (OWNW * w + lane) : (OWNW * w - HALO + lane);
    const bool owner = dir ? (lane < OWNW && p < NSNAP)
                           : (lane >= HALO && p < NSNAP);

    const int  pc   = min(max(p, 0), Lmax - 1);
    const int  lab  = labels[b * Lmax + pc];
    const int  labn = labels[b * Lmax + min(pc + 1, Lmax - 1)];
    const bool allow  = (p > 0) && (lab != labels[b * Lmax + max(pc - 1, 0)]);
    const bool allown = (labn != lab);
    const bool vE = (p >= 0) && (p <= label_len);
    const bool vO = (p >= 0) && (p <  label_len);

    const float* base = logits + (size_t)b * Vv;
    const size_t gstr = (size_t)Bb * Vv;

    int su[NSTG], svv[NSTG]; bool sa[NSTG];
#pragma unroll
    for (int i = 0; i < NSTG; i++) {
        int idx = tid + i * THR;
        sa[i]  = idx < UU * Vv;
        su[i]  = idx / Vv;
        svv[i] = idx - su[i] * Vv;
    }

    for (int i = tid; i < NSNAP; i += THR) {
        snap[0][i] = make_float2(NEGV, NEGV);
        snap[1][i] = make_float2(NEGV, NEGV);
    }
    __syncthreads();
    if (tid == 0) {
        if (dir == 0) {
            int lab0 = labels[b * Lmax];
            snap[0][0] = make_float2(base[0] * LOG2E, base[lab0] * LOG2E);
        } else {
            snap[0][label_len]     = make_float2(0.f, NEGV);
            snap[0][label_len - 1] = make_float2(NEGV, 0.f);
        }
    }
    float g[NSTG];
#pragma unroll
    for (int i = 0; i < NSTG; i++) {
        if (sa[i]) {
            int j1 = min(su[i], NST - 1);
            int r1 = dir ? (act_len - 1 - j1) : (1 + j1);
            rbuf[0][su[i] * RSTR + svv[i]] = base[(size_t)r1 * gstr + svv[i]] * LOG2E;
            int j2 = min(UU + su[i], NST - 1);
            int r2 = dir ? (act_len - 1 - j2) : (1 + j2);
            g[i] = base[(size_t)r2 * gstr + svv[i]];
        }
    }
    __syncthreads();

    float aE = NEGV, aO = NEGV;
    int scur = 0, rcur = 0;
    for (int j0 = 0; j0 < NST; j0 += UU) {
        const int rnxt = (rcur + 1) % 3;
        const float* rb = rbuf[rcur];
        float lpB[UU], lpL[UU], lpLn[UU];
#pragma unroll
        for (int u = 0; u < UU; u++) {
            lpB[u] = rb[u * RSTR];
            lpL[u] = rb[u * RSTR + lab];
            if (dir) lpLn[u] = rb[u * RSTR + labn];
        }
#pragma unroll
        for (int i = 0; i < NSTG; i++)
            if (sa[i]) rbuf[rnxt][su[i] * RSTR + svv[i]] = g[i] * LOG2E;
#pragma unroll
        for (int i = 0; i < NSTG; i++) {
            if (sa[i]) {
                int j2 = min(j0 + 2 * UU + su[i], NST - 1);
                int r2 = dir ? (act_len - 1 - j2) : (1 + j2);
                g[i] = base[(size_t)r2 * gstr + svv[i]];
            }
        }

        float2 P = (p >= 0 && p < NSNAP) ? snap[scur][p] : make_float2(NEGV, NEGV);
        aE = P.x; aO = P.y;

        if (dir == 0) {
#pragma unroll
            for (int u = 0; u < UU; u++) {
                const bool live = (j0 + u) < NST;
                float aOp = __shfl_up_sync(0xffffffffu, aO, 1);
                float M1 = fmaxf(aO, aE), m1 = fminf(aO, aE);
                if (lane == 0) aOp = NEGV;
                float c  = allow ? aOp : NEGV;
                float ME = fmaxf(aE, aOp), mE = fminf(aE, aOp);
                float nE = lg2f_(1.0f + ex2f_(mE - ME)) + (ME + lpB[u]);
                float M2 = fmaxf(M1, c), m2 = fminf(M1, c);
                float nO = lg2f_(1.0f + ex2f_(m1 - M2) + ex2f_(m2 - M2)) + (M2 + lpL[u]);
                if (live) { aE = vE ? nE : NEGV; aO = vO ? nO : NEGV; }
            }
        } else {
#pragma unroll
            for (int u = 0; u < UU; u++) {
                const bool live = (j0 + u) < NST;
                float aEn = __shfl_down_sync(0xffffffffu, aE, 1);
                float aOn = __shfl_down_sync(0xffffffffu, aO, 1);
                float tE = aE + lpB[u];
                float tO = aO + lpL[u];
                if (lane == 31) { aEn = NEGV; aOn = NEGV; }
                float t2 = aEn + lpB[u];
                float t3 = allown ? (aOn + lpLn[u]) : NEGV;
                float nE = lae2_(tE, tO);
                float nO = lae3_(tO, t2, t3);
                if (live) { aE = vE ? nE : NEGV; aO = vO ? nO : NEGV; }
            }
        }

        if (owner) snap[scur ^ 1][p] = make_float2(aE, aO);
        __syncthreads();
        scur ^= 1;
        rcur = rnxt;
    }

    if (owner) g_ab[dir][b][p] = make_float2(aE, aO);
}

__global__ void finalize_kernel(const int* __restrict__ act_lens) {
    const int b = blockIdx.x, tid = threadIdx.x;
    const int n = act_lens[b];

    float x = NEGV, y = NEGV;
    if (tid < NSNAP) {
        float2 va = g_ab[0][b][tid];
        float2 vb = g_ab[1][b][tid];
        x = va.x + vb.x;
        y = va.y + vb.y;
    }
    __shared__ float redf[256];
    float m = fmaxf(x, y);
    redf[tid] = m; __syncthreads();
    for (int o = 128; o > 0; o >>= 1) {
        if (tid < o) redf[tid] = fmaxf(redf[tid], redf[tid + o]);
        __syncthreads();
    }
    const float gm = redf[0];
    __syncthreads();
    float sv = ex2f_(x - gm) + ex2f_(y - gm);
    redf[tid] = sv; __syncthreads();
    for (int o = 128; o > 0; o >>= 1) {
        if (tid < o) redf[tid] += redf[tid + o];
        __syncthreads();
    }
    const float ll2raw = gm + lg2f_(redf[0]);
    __syncthreads();

    const float* pr = g_lse2 + (size_t)b * Tt;
    double sd = 0.0;
    for (int t = tid; t < n; t += 256) sd += (double)pr[t];
    __shared__ double redd[256];
    redd[tid] = sd; __syncthreads();
    for (int o = 128; o > 0; o >>= 1) {
        if (tid < o) redd[tid] += redd[tid + o];
        __syncthreads();
    }
    if (tid == 0)
        g_losses[b] = (float)((redd[0] - (double)ll2raw) * (double)LN2);
}

__global__ void reduce_kernel(const int* __restrict__ act_lens,
                              float* __restrict__ out)
{
    int lane = threadIdx.x;
    float l = g_losses[lane] + g_losses[lane + 32];
    float n = (float)act_lens[lane] + (float)act_lens[lane + 32];
#pragma unroll
    for (int o = 16; o > 0; o >>= 1) {
        l += __shfl_xor_sync(0xffffffffu, l, o);
        n += __shfl_xor_sync(0xffffffffu, n, o);
    }
    if (lane == 0) out[0] = l / n;
}

extern "C" void kernel_launch(void* const* d_in, const int* in_sizes, int n_in,
                              void* d_out, int out_size)
{
    const float* logits     = (const float*)d_in[0];
    const int*   labels     = (const int*)  d_in[1];
    const int*   act_lens   = (const int*)  d_in[2];
    const int*   label_lens = (const int*)  d_in[3];

    const int rows = Tt * Bb;
    lse_kernel<<<(rows * 32 + 255) / 256, 256>>>(logits);
    ctc_ab_kernel<<<dim3(Bb, 2), THR>>>(logits, labels, act_lens, label_lens);
    finalize_kernel<<<Bb, 256>>>(act_lens);
    reduce_kernel<<<1, 32>>>(act_lens, (float*)d_out);
}